// round 10
// baseline (speedup 1.0000x reference)
#include <cuda_runtime.h>
#include <math.h>

#define NRR 512
#define NAA 512
#define KC 8               // gaussian chunks per tile (balance factor)
#define NTILES 256         // 16x16 tiles of 32x32 px

// Scratch (device globals; no allocs).
__device__ float g_part[KC][NRR * NAA];   // per-chunk partial images (exclusive writes)
__device__ int   g_tick[NTILES];          // per-tile completion tickets (self-resetting)

// Single fused kernel: prep + cull + splat + tree-reduce.
// Block = (tile x, tile y, chunk z). 256 threads: 32 cols x 8 row-groups, 4 rows/thread.
__global__ __launch_bounds__(256) void sar_kernel(
    const float* __restrict__ pos,
    const float* __restrict__ cov,
    const float* __restrict__ inten,
    float* __restrict__ out, int N)
{
    __shared__ float4 sP0[256];       // (rc, cc, A, B)
    __shared__ float4 sP1[256];       // (C, w, -, -)
    __shared__ int    warpTot[8];
    __shared__ int    warpOff[8];
    __shared__ int    sCount;
    __shared__ int    sLast;

    const int tid  = threadIdx.x;
    const int lane = tid & 31;
    const int wid  = tid >> 5;
    const int tx   = tid & 31;
    const int ty   = tid >> 5;

    const int chunk  = blockIdx.z;
    const int tileId = blockIdx.y * 16 + blockIdx.x;
    const int cbeg   = (chunk * N) / KC;
    const int cend   = ((chunk + 1) * N) / KC;

    const int   col  = blockIdx.x * 32 + tx;
    const int   rowb = blockIdx.y * 32;
    const float colf = (float)col;
    const float rf0  = (float)(rowb + ty);
    const float r0   = (float)rowb;
    const float c0   = (float)(blockIdx.x * 32);

    const float cbeta = 0.8660254037844387f;   // cos(30deg)
    const float sbeta = 0.5f;                  // sin(30deg)
    const float RCc   = 5773.502691896258f;    // ALT/cos(beta)
    const float RPY   = -2886.7513459481287f;  // radar pos y
    const float RPZ   = 5000.0f;
    const float L2E   = 1.4426950408889634f;

    float acc0 = 0.f, acc1 = 0.f, acc2 = 0.f, acc3 = 0.f;

    for (int base = cbeg; base < cend; base += 256) {
        // ---- fused prep + cull: one gaussian per thread, in registers ----
        const int n = base + tid;
        bool  ok = false;
        float rc = 0.f, cc = 0.f, A = 0.f, B = 0.f, C = 0.f, w = 0.f;
        if (n < cend) {
            float dx = pos[n*3+0];
            float dy = pos[n*3+1] - RPY;
            float dz = pos[n*3+2] - RPZ;

            float Xr = dx;
            float Yr = -cbeta*dy - sbeta*dz;
            float Zr =  sbeta*dy - cbeta*dz;

            float Rmin = sqrtf(Yr*Yr + Zr*Zr + 1e-12f);
            rc = Rmin + 256.0f - RCc;
            cc = Xr + 256.0f;
            float u1 = Yr / Rmin;
            float u2 = Zr / Rmin;

            const float* S = cov + n*9;
            float S00=S[0], S01=S[1], S02=S[2], S11=S[4], S12=S[5], S22=S[8];

            float c10 = -cbeta*S01 - sbeta*S02;
            float c20 =  sbeta*S01 - cbeta*S02;
            float c11 = cbeta*cbeta*S11 + 2.0f*cbeta*sbeta*S12 + sbeta*sbeta*S22;
            float c12 = cbeta*sbeta*(S22 - S11) + (cbeta*cbeta - sbeta*sbeta)*S12;
            float c22 = sbeta*sbeta*S11 - 2.0f*sbeta*cbeta*S12 + cbeta*cbeta*S22;

            float a  = u1*u1*c11 + 2.0f*u1*u2*c12 + u2*u2*c22 + 1e-4f;
            float b  = u1*c10 + u2*c20;
            float d2 = S00 + 1e-4f;

            float det = a*d2 - b*b;
            float inv = 1.0f / det;
            A = -0.5f * L2E * d2 * inv;
            B =         L2E * b  * inv;
            C = -0.5f * L2E * a  * inv;
            w = inten[n] * 0.15915494309189535f * inv;

            // mahal > 40: boundary contribution <= exp(-20)*w ~ 2e-9 vs image
            // values O(0.1-1) and 1e-3 global tolerance -> 5+ orders of margin.
            const float T = 40.0f;
            float er = sqrtf(T * a);
            float ec = sqrtf(T * d2);

            ok = (rc + er >= r0) && (rc - er <= r0 + 31.0f) &&
                 (cc + ec >= c0) && (cc - ec <= c0 + 31.0f);
        }

        unsigned bal = __ballot_sync(0xffffffffu, ok);
        if (lane == 0) warpTot[wid] = __popc(bal);
        __syncthreads();
        if (tid == 0) {
            int s = 0;
            #pragma unroll
            for (int w2 = 0; w2 < 8; w2++) { warpOff[w2] = s; s += warpTot[w2]; }
            sCount = s;
        }
        __syncthreads();
        if (ok) {
            int off = warpOff[wid] + __popc(bal & ((1u << lane) - 1u));
            sP0[off] = make_float4(rc, cc, A, B);
            sP1[off] = make_float4(C, w, 0.f, 0.f);
        }
        __syncthreads();

        // ---- splat survivors: 4 rows per thread ----
        const int M = sCount;
        #pragma unroll 2
        for (int i = 0; i < M; i++) {
            const float4 p0 = sP0[i];   // uniform -> broadcast LDS
            const float4 p1 = sP1[i];

            float dc  = colf - p0.y;
            float Bdc = p0.w * dc;
            float Cq  = p1.x * dc * dc;
            float drb = rf0 - p0.x;

            float dr0 = drb;
            float dr1 = drb + 8.0f;
            float dr2 = drb + 16.0f;
            float dr3 = drb + 24.0f;

            float t0 = fmaf(p0.z, dr0, Bdc);
            float t1 = fmaf(p0.z, dr1, Bdc);
            float t2 = fmaf(p0.z, dr2, Bdc);
            float t3 = fmaf(p0.z, dr3, Bdc);

            float m0 = fmaf(t0, dr0, Cq);
            float m1 = fmaf(t1, dr1, Cq);
            float m2 = fmaf(t2, dr2, Cq);
            float m3 = fmaf(t3, dr3, Cq);

            float e0, e1, e2, e3;
            asm("ex2.approx.ftz.f32 %0, %1;" : "=f"(e0) : "f"(m0));
            asm("ex2.approx.ftz.f32 %0, %1;" : "=f"(e1) : "f"(m1));
            asm("ex2.approx.ftz.f32 %0, %1;" : "=f"(e2) : "f"(m2));
            asm("ex2.approx.ftz.f32 %0, %1;" : "=f"(e3) : "f"(m3));

            acc0 = fmaf(p1.y, e0, acc0);
            acc1 = fmaf(p1.y, e1, acc1);
            acc2 = fmaf(p1.y, e2, acc2);
            acc3 = fmaf(p1.y, e3, acc3);
        }
        __syncthreads();
    }

    // ---- write partial ----
    const int i0 = (rowb + ty      ) * NAA + col;
    const int i1 = (rowb + ty +  8 ) * NAA + col;
    const int i2 = (rowb + ty + 16 ) * NAA + col;
    const int i3 = (rowb + ty + 24 ) * NAA + col;
    float* dst = g_part[chunk];
    dst[i0] = acc0; dst[i1] = acc1; dst[i2] = acc2; dst[i3] = acc3;

    // ---- last block of this tile reduces (fixed chunk order -> deterministic) ----
    __threadfence();
    __syncthreads();
    if (tid == 0) {
        int old = atomicAdd(&g_tick[tileId], 1);
        sLast = (old == KC - 1) ? 1 : 0;
    }
    __syncthreads();
    if (sLast) {
        #pragma unroll
        for (int k = 0; k < 4; k++) {
            int i = (k == 0) ? i0 : (k == 1) ? i1 : (k == 2) ? i2 : i3;
            float s0 = g_part[0][i] + g_part[1][i];
            float s1 = g_part[2][i] + g_part[3][i];
            float s2 = g_part[4][i] + g_part[5][i];
            float s3 = g_part[6][i] + g_part[7][i];
            out[i] = (s0 + s1) + (s2 + s3);
        }
        if (tid == 0) g_tick[tileId] = 0;   // self-reset for next graph replay
    }
}

extern "C" void kernel_launch(void* const* d_in, const int* in_sizes, int n_in,
                              void* d_out, int out_size)
{
    const float* pos   = (const float*)d_in[0];
    const float* cov   = (const float*)d_in[1];
    const float* inten = (const float*)d_in[2];
    float* out = (float*)d_out;

    int N = in_sizes[2];   // N_GAUSS

    dim3 grd(NAA / 32, NRR / 32, KC);
    sar_kernel<<<grd, 256>>>(pos, cov, inten, out, N);
}

// round 11
// speedup vs baseline: 1.2179x; 1.2179x over previous
#include <cuda_runtime.h>
#include <math.h>

#define NRR 512
#define NAA 512
#define KC 4               // gaussian chunks per tile (1024 blocks = one wave)
#define NTILES 256         // 16x16 tiles of 32x32 px

// Scratch (device globals; no allocs).
__device__ float g_part[KC][NRR * NAA];   // per-chunk partial images (exclusive writes)
__device__ int   g_tick[NTILES];          // per-tile completion tickets (self-resetting)

// Single fused kernel: prep + cull + splat + tree-reduce.
// Block = (tile x, tile y, chunk z). 256 threads: 32 cols x 8 row-groups, 4 rows/thread.
__global__ __launch_bounds__(256) void sar_kernel(
    const float* __restrict__ pos,
    const float* __restrict__ cov,
    const float* __restrict__ inten,
    float* __restrict__ out, int N)
{
    __shared__ float4 sP0[256];       // (rc, cc, A, B)
    __shared__ float4 sP1[256];       // (C, w, -, -)
    __shared__ int    warpTot[8];
    __shared__ int    warpOff[8];
    __shared__ int    sCount;
    __shared__ int    sLast;

    const int tid  = threadIdx.x;
    const int lane = tid & 31;
    const int wid  = tid >> 5;
    const int tx   = tid & 31;
    const int ty   = tid >> 5;

    const int chunk  = blockIdx.z;
    const int tileId = blockIdx.y * 16 + blockIdx.x;
    const int cbeg   = (chunk * N) / KC;
    const int cend   = ((chunk + 1) * N) / KC;

    const int   col  = blockIdx.x * 32 + tx;
    const int   rowb = blockIdx.y * 32;
    const float colf = (float)col;
    const float rf0  = (float)(rowb + ty);
    const float r0   = (float)rowb;
    const float c0   = (float)(blockIdx.x * 32);

    const float cbeta = 0.8660254037844387f;   // cos(30deg)
    const float sbeta = 0.5f;                  // sin(30deg)
    const float RCc   = 5773.502691896258f;    // ALT/cos(beta)
    const float RPY   = -2886.7513459481287f;  // radar pos y
    const float RPZ   = 5000.0f;
    const float L2E   = 1.4426950408889634f;

    float acc0 = 0.f, acc1 = 0.f, acc2 = 0.f, acc3 = 0.f;

    for (int base = cbeg; base < cend; base += 256) {
        // ---- fused prep + cull: one gaussian per thread, in registers ----
        const int n = base + tid;
        bool  ok = false;
        float rc = 0.f, cc = 0.f, A = 0.f, B = 0.f, C = 0.f, w = 0.f;
        if (n < cend) {
            float dx = pos[n*3+0];
            float dy = pos[n*3+1] - RPY;
            float dz = pos[n*3+2] - RPZ;

            float Xr = dx;
            float Yr = -cbeta*dy - sbeta*dz;
            float Zr =  sbeta*dy - cbeta*dz;

            float Rmin = sqrtf(Yr*Yr + Zr*Zr + 1e-12f);
            rc = Rmin + 256.0f - RCc;
            cc = Xr + 256.0f;
            float u1 = Yr / Rmin;
            float u2 = Zr / Rmin;

            const float* S = cov + n*9;
            float S00=S[0], S01=S[1], S02=S[2], S11=S[4], S12=S[5], S22=S[8];

            float c10 = -cbeta*S01 - sbeta*S02;
            float c20 =  sbeta*S01 - cbeta*S02;
            float c11 = cbeta*cbeta*S11 + 2.0f*cbeta*sbeta*S12 + sbeta*sbeta*S22;
            float c12 = cbeta*sbeta*(S22 - S11) + (cbeta*cbeta - sbeta*sbeta)*S12;
            float c22 = sbeta*sbeta*S11 - 2.0f*sbeta*cbeta*S12 + cbeta*cbeta*S22;

            float a  = u1*u1*c11 + 2.0f*u1*u2*c12 + u2*u2*c22 + 1e-4f;
            float b  = u1*c10 + u2*c20;
            float d2 = S00 + 1e-4f;

            float det = a*d2 - b*b;
            float inv = 1.0f / det;
            A = -0.5f * L2E * d2 * inv;
            B =         L2E * b  * inv;
            C = -0.5f * L2E * a  * inv;
            w = inten[n] * 0.15915494309189535f * inv;

            // mahal > 40: boundary contribution <= exp(-20)*w ~ 2e-9 vs image
            // values O(0.1-1) and 1e-3 global tolerance (validated: rel_err
            // stays 2.26e-7 at T=40).
            const float T = 40.0f;
            float er = sqrtf(T * a);
            float ec = sqrtf(T * d2);

            ok = (rc + er >= r0) && (rc - er <= r0 + 31.0f) &&
                 (cc + ec >= c0) && (cc - ec <= c0 + 31.0f);
        }

        unsigned bal = __ballot_sync(0xffffffffu, ok);
        if (lane == 0) warpTot[wid] = __popc(bal);
        __syncthreads();
        if (tid == 0) {
            int s = 0;
            #pragma unroll
            for (int w2 = 0; w2 < 8; w2++) { warpOff[w2] = s; s += warpTot[w2]; }
            sCount = s;
        }
        __syncthreads();
        if (ok) {
            int off = warpOff[wid] + __popc(bal & ((1u << lane) - 1u));
            sP0[off] = make_float4(rc, cc, A, B);
            sP1[off] = make_float4(C, w, 0.f, 0.f);
        }
        __syncthreads();

        // ---- splat survivors: 4 rows per thread ----
        const int M = sCount;
        #pragma unroll 2
        for (int i = 0; i < M; i++) {
            const float4 p0 = sP0[i];   // uniform -> broadcast LDS
            const float4 p1 = sP1[i];

            float dc  = colf - p0.y;
            float Bdc = p0.w * dc;
            float Cq  = p1.x * dc * dc;
            float drb = rf0 - p0.x;

            float dr0 = drb;
            float dr1 = drb + 8.0f;
            float dr2 = drb + 16.0f;
            float dr3 = drb + 24.0f;

            float t0 = fmaf(p0.z, dr0, Bdc);
            float t1 = fmaf(p0.z, dr1, Bdc);
            float t2 = fmaf(p0.z, dr2, Bdc);
            float t3 = fmaf(p0.z, dr3, Bdc);

            float m0 = fmaf(t0, dr0, Cq);
            float m1 = fmaf(t1, dr1, Cq);
            float m2 = fmaf(t2, dr2, Cq);
            float m3 = fmaf(t3, dr3, Cq);

            float e0, e1, e2, e3;
            asm("ex2.approx.ftz.f32 %0, %1;" : "=f"(e0) : "f"(m0));
            asm("ex2.approx.ftz.f32 %0, %1;" : "=f"(e1) : "f"(m1));
            asm("ex2.approx.ftz.f32 %0, %1;" : "=f"(e2) : "f"(m2));
            asm("ex2.approx.ftz.f32 %0, %1;" : "=f"(e3) : "f"(m3));

            acc0 = fmaf(p1.y, e0, acc0);
            acc1 = fmaf(p1.y, e1, acc1);
            acc2 = fmaf(p1.y, e2, acc2);
            acc3 = fmaf(p1.y, e3, acc3);
        }
        __syncthreads();
    }

    // ---- write partial ----
    const int i0 = (rowb + ty      ) * NAA + col;
    const int i1 = (rowb + ty +  8 ) * NAA + col;
    const int i2 = (rowb + ty + 16 ) * NAA + col;
    const int i3 = (rowb + ty + 24 ) * NAA + col;
    float* dst = g_part[chunk];
    dst[i0] = acc0; dst[i1] = acc1; dst[i2] = acc2; dst[i3] = acc3;

    // ---- last block of this tile reduces (fixed chunk order -> deterministic) ----
    __threadfence();
    __syncthreads();
    if (tid == 0) {
        int old = atomicAdd(&g_tick[tileId], 1);
        sLast = (old == KC - 1) ? 1 : 0;
    }
    __syncthreads();
    if (sLast) {
        out[i0] = ((g_part[0][i0] + g_part[1][i0]) + (g_part[2][i0] + g_part[3][i0]));
        out[i1] = ((g_part[0][i1] + g_part[1][i1]) + (g_part[2][i1] + g_part[3][i1]));
        out[i2] = ((g_part[0][i2] + g_part[1][i2]) + (g_part[2][i2] + g_part[3][i2]));
        out[i3] = ((g_part[0][i3] + g_part[1][i3]) + (g_part[2][i3] + g_part[3][i3]));
        if (tid == 0) g_tick[tileId] = 0;   // self-reset for next graph replay
    }
}

extern "C" void kernel_launch(void* const* d_in, const int* in_sizes, int n_in,
                              void* d_out, int out_size)
{
    const float* pos   = (const float*)d_in[0];
    const float* cov   = (const float*)d_in[1];
    const float* inten = (const float*)d_in[2];
    float* out = (float*)d_out;

    int N = in_sizes[2];   // N_GAUSS

    dim3 grd(NAA / 32, NRR / 32, KC);
    sar_kernel<<<grd, 256>>>(pos, cov, inten, out, N);
}